// round 2
// baseline (speedup 1.0000x reference)
#include <cuda_runtime.h>
#include <math.h>

// ---------------------------------------------------------------------------
// AdvancedAutoInformer — reduced-domain implementation.
// Output depends only on token t=3999. Attention is block-local (BLOCK=20,
// aligned blocks), LN/FF pointwise in time, convs have +-2 receptive field.
// => compute only tokens t in [3980,4000) from x[t in 3978..3999].
// Shapes: B=32, S=20 tokens, D=256, H=8 heads, hd=32, F=1024, L=4 layers.
// ---------------------------------------------------------------------------

#define BATCH 32
#define SEQ   20
#define NTOK  (BATCH*SEQ)     // 640

// Scratch (static device arrays; no runtime allocation).
__device__ __align__(16) float g_c1col[NTOK*768];   // im2col of conv1 output
__device__ __align__(16) float g_hf  [NTOK*256];
__device__ __align__(16) float g_h   [NTOK*256];
__device__ __align__(16) float g_qkv [NTOK*768];
__device__ __align__(16) float g_hid [NTOK*1024];
__device__ __align__(16) float g_ff  [NTOK*256];
__device__ __align__(16) float g_att [NTOK*256];
__device__ __align__(16) float g_part[4*NTOK*256];  // FF2 split-K partials

__device__ __forceinline__ float* resolve(int s){
  switch(s){
    case 0: return g_c1col;
    case 1: return g_hf;
    case 2: return g_h;
    case 3: return g_qkv;
    case 4: return g_hid;
    case 5: return g_ff;
    case 6: return g_att;
    case 7: return g_part;
  }
  return nullptr;
}

// ---------------------------------------------------------------------------
// conv1 (C=16 -> D=256, k=3, SAME) + relu, scattered directly into im2col
// layout for the conv2 GEMM: g_c1col[(b*20+i)*768 + d*3 + k] = c1[b, t0-1+i+k, d]
// ---------------------------------------------------------------------------
__global__ void conv1_kernel(const float* __restrict__ x,
                             const float* __restrict__ w,
                             const float* __restrict__ bias){
  __shared__ float xs[23*16];          // t = 3978..3999, row 22 = zero pad (t=4000)
  int b = blockIdx.x, tid = threadIdx.x;
  for (int idx = tid; idx < 23*16; idx += 256){
    int j = idx >> 4, c = idx & 15;
    int t = 3978 + j;
    xs[idx] = (t < 4000) ? x[(b*4000 + t)*16 + c] : 0.f;
  }
  __syncthreads();
  int d = tid;
  float wr[48];
  #pragma unroll
  for (int q = 0; q < 48; q++) wr[q] = w[d*48 + q];
  float bb = bias[d];
  // p indexes c1 at global t = 3979+p; p=21 is the zero pad (t=4000).
  for (int p = 0; p < 22; p++){
    float val = 0.f;
    if (p < 21){
      float acc = bb;
      #pragma unroll
      for (int k = 0; k < 3; k++)
        #pragma unroll
        for (int c = 0; c < 16; c++)
          acc += wr[c*3 + k] * xs[(p + k)*16 + c];
      val = fmaxf(acc, 0.f);
    }
    #pragma unroll
    for (int k = 0; k < 3; k++){
      int i = p - k;
      if (i >= 0 && i < 20)
        g_c1col[(b*20 + i)*768 + d*3 + k] = val;
    }
  }
}

// ---------------------------------------------------------------------------
// Generic tiled GEMM: C[m][n] = sum_k A[m][k0+k] * W[n][k0+k]  (NT layout)
// A: scratch selector (M=640 rows, row stride lda). W: (N x ldw) row-major.
// blockIdx.z gives split-K chunk: k0 = z*klen, C += z*czstride.
// Epilogue modes:
//   0: +bias   1: relu(+bias)   2 (DUAL): R + (acc1+b1) + sin(acc2+b2)
//   3: +bias +R                 4: raw partial store
// ---------------------------------------------------------------------------
template<int BM, int BN, int DUAL>
__global__ void gemm_k(int a_sel, int lda, int klen,
                       const float* __restrict__ W,
                       const float* __restrict__ W2, int ldw,
                       const float* __restrict__ b1,
                       const float* __restrict__ b2,
                       int r_sel, int c_sel, int N, int czstride, int mode)
{
  constexpr int NT = (BM/4)*(BN/4);
  constexpr int LA = BM + 4, LB = BN + 4;
  __shared__ float As[16*LA];
  __shared__ float Ws[16*LB];
  __shared__ float Ws2[DUAL ? 16*LB : 4];

  const float* A = resolve(a_sel);
  float* C = resolve(c_sel) + blockIdx.z * czstride;
  int tid = threadIdx.x;
  int tx = tid % (BN/4), ty = tid / (BN/4);
  int m0 = blockIdx.y * BM, n0 = blockIdx.x * BN;
  int k0 = blockIdx.z * klen;

  float acc[16];
  float acc2[DUAL ? 16 : 1];
  #pragma unroll
  for (int q = 0; q < 16; q++) acc[q] = 0.f;
  if (DUAL){
    #pragma unroll
    for (int q = 0; q < (DUAL ? 16 : 1); q++) acc2[q] = 0.f;
  }

  for (int kt = 0; kt < klen; kt += 16){
    // Load A tile transposed: As[k][m]
    for (int idx = tid; idx < BM*4; idx += NT){
      int r = idx >> 2, c4 = idx & 3;
      const float4 v = *(const float4*)&A[(m0 + r)*lda + k0 + kt + c4*4];
      As[(c4*4+0)*LA + r] = v.x;
      As[(c4*4+1)*LA + r] = v.y;
      As[(c4*4+2)*LA + r] = v.z;
      As[(c4*4+3)*LA + r] = v.w;
    }
    // Load W tile transposed: Ws[k][n]
    for (int idx = tid; idx < BN*4; idx += NT){
      int r = idx >> 2, c4 = idx & 3;
      const float4 v = *(const float4*)&W[(n0 + r)*ldw + k0 + kt + c4*4];
      Ws[(c4*4+0)*LB + r] = v.x;
      Ws[(c4*4+1)*LB + r] = v.y;
      Ws[(c4*4+2)*LB + r] = v.z;
      Ws[(c4*4+3)*LB + r] = v.w;
      if (DUAL){
        const float4 u = *(const float4*)&W2[(n0 + r)*ldw + k0 + kt + c4*4];
        Ws2[(c4*4+0)*LB + r] = u.x;
        Ws2[(c4*4+1)*LB + r] = u.y;
        Ws2[(c4*4+2)*LB + r] = u.z;
        Ws2[(c4*4+3)*LB + r] = u.w;
      }
    }
    __syncthreads();
    #pragma unroll
    for (int k = 0; k < 16; k++){
      float4 a = *(const float4*)&As[k*LA + ty*4];
      float4 w = *(const float4*)&Ws[k*LB + tx*4];
      acc[ 0] += a.x*w.x; acc[ 1] += a.x*w.y; acc[ 2] += a.x*w.z; acc[ 3] += a.x*w.w;
      acc[ 4] += a.y*w.x; acc[ 5] += a.y*w.y; acc[ 6] += a.y*w.z; acc[ 7] += a.y*w.w;
      acc[ 8] += a.z*w.x; acc[ 9] += a.z*w.y; acc[10] += a.z*w.z; acc[11] += a.z*w.w;
      acc[12] += a.w*w.x; acc[13] += a.w*w.y; acc[14] += a.w*w.z; acc[15] += a.w*w.w;
      if (DUAL){
        float4 u = *(const float4*)&Ws2[k*LB + tx*4];
        acc2[ 0] += a.x*u.x; acc2[ 1] += a.x*u.y; acc2[ 2] += a.x*u.z; acc2[ 3] += a.x*u.w;
        acc2[ 4] += a.y*u.x; acc2[ 5] += a.y*u.y; acc2[ 6] += a.y*u.z; acc2[ 7] += a.y*u.w;
        acc2[ 8] += a.z*u.x; acc2[ 9] += a.z*u.y; acc2[10] += a.z*u.z; acc2[11] += a.z*u.w;
        acc2[12] += a.w*u.x; acc2[13] += a.w*u.y; acc2[14] += a.w*u.z; acc2[15] += a.w*u.w;
      }
    }
    __syncthreads();
  }

  const float* R = (r_sel >= 0) ? resolve(r_sel) : nullptr;
  #pragma unroll
  for (int r = 0; r < 4; r++){
    int m = m0 + ty*4 + r;
    #pragma unroll
    for (int c = 0; c < 4; c++){
      int n = n0 + tx*4 + c;
      float v = acc[r*4 + c];
      if (mode == 0)      v += b1[n];
      else if (mode == 1) v = fmaxf(v + b1[n], 0.f);
      else if (DUAL && mode == 2)
        v = R[m*N + n] + (v + b1[n]) + sinf(acc2[DUAL ? (r*4 + c) : 0] + b2[n]);
      else if (mode == 3) v += b1[n] + R[m*N + n];
      // mode 4: raw
      C[m*N + n] = v;
    }
  }
}

// ---------------------------------------------------------------------------
// Per-batch block attention: 8 heads, 20x20 scores, softmax, o = a@v.
// Reads g_qkv (layout [640][768]: q|k|v each 256 = 8 heads x 32), writes g_att.
// ---------------------------------------------------------------------------
__global__ void attn_kernel(){
  int b = blockIdx.x, tid = threadIdx.x;
  __shared__ float skv[20*512];        // k (e 0..255) | v (e 256..511) per token
  const float* qkv = g_qkv + b*20*768;
  for (int idx = tid; idx < 20*512; idx += 256){
    int i = idx >> 9, e = idx & 511;
    skv[idx] = qkv[i*768 + 256 + e];
  }
  __syncthreads();
  if (tid < 160){
    int h = tid / 20, i = tid % 20;
    float qr[32];
    const float* qp = qkv + i*768 + h*32;
    #pragma unroll
    for (int t = 0; t < 32; t++) qr[t] = qp[t];
    float sc[20];
    float mx = -1e30f;
    for (int j = 0; j < 20; j++){
      const float* kp = &skv[j*512 + h*32];
      float d = 0.f;
      #pragma unroll
      for (int t = 0; t < 32; t++) d += qr[t]*kp[t];
      d *= 0.17677669529663687f;   // 1/sqrt(32)
      sc[j] = d;
      mx = fmaxf(mx, d);
    }
    float s = 0.f;
    for (int j = 0; j < 20; j++){ sc[j] = expf(sc[j] - mx); s += sc[j]; }
    float inv = 1.f / s;
    float* op = g_att + (b*20 + i)*256 + h*32;
    for (int d0 = 0; d0 < 32; d0++){
      float o = 0.f;
      for (int j = 0; j < 20; j++) o += sc[j]*skv[j*512 + 256 + h*32 + d0];
      op[d0] = o * inv;
    }
  }
}

// ---------------------------------------------------------------------------
// LayerNorm helpers (block = 256 threads = one token row).
// ---------------------------------------------------------------------------
__device__ __forceinline__ float block_sum256(float v, float* sh){
  #pragma unroll
  for (int o = 16; o > 0; o >>= 1) v += __shfl_xor_sync(0xffffffffu, v, o);
  if ((threadIdx.x & 31) == 0) sh[threadIdx.x >> 5] = v;
  __syncthreads();
  if (threadIdx.x == 0){
    float s = 0.f;
    #pragma unroll
    for (int w = 0; w < 8; w++) s += sh[w];
    sh[0] = s;
  }
  __syncthreads();
  float r = sh[0];
  __syncthreads();
  return r;
}

__global__ void ln_kernel(int x_sel, int r_sel,
                          const float* __restrict__ g,
                          const float* __restrict__ bta, int o_sel){
  __shared__ float sh[8];
  const float* X = resolve(x_sel);
  const float* R = (r_sel >= 0) ? resolve(r_sel) : nullptr;
  float* O = resolve(o_sel);
  int m = blockIdx.x, d = threadIdx.x;
  float v = X[m*256 + d] + (R ? R[m*256 + d] : 0.f);
  float mean = block_sum256(v, sh) * (1.f/256.f);
  float c = v - mean;
  float var = block_sum256(c*c, sh) * (1.f/256.f);
  O[m*256 + d] = c * rsqrtf(var + 1e-5f) * g[d] + bta[d];
}

__global__ void ln_ff2_kernel(const float* __restrict__ bias,
                              const float* __restrict__ g,
                              const float* __restrict__ bta){
  __shared__ float sh[8];
  int m = blockIdx.x, d = threadIdx.x;
  int idx = m*256 + d;
  float v = g_h[idx] + bias[d]
          + g_part[idx] + g_part[NTOK*256 + idx]
          + g_part[2*NTOK*256 + idx] + g_part[3*NTOK*256 + idx];
  float mean = block_sum256(v, sh) * (1.f/256.f);
  float c = v - mean;
  float var = block_sum256(c*c, sh) * (1.f/256.f);
  g_h[idx] = c * rsqrtf(var + 1e-5f) * g[d] + bta[d];
}

// ---------------------------------------------------------------------------
// Final projection: out[b] = h[b, last] @ fc_w^T + fc_b.
// ---------------------------------------------------------------------------
__global__ void final_kernel(const float* __restrict__ fw,
                             const float* __restrict__ fb,
                             float* __restrict__ out){
  int tid = threadIdx.x;
  int b = tid >> 4, c = tid & 15;
  const float* hr = g_h + (b*20 + 19)*256;
  const float* wr = fw + c*256;
  float acc = fb[c];
  for (int d = 0; d < 256; d++) acc += hr[d]*wr[d];
  out[tid] = acc;
}

// ---------------------------------------------------------------------------
extern "C" void kernel_launch(void* const* d_in, const int* in_sizes, int n_in,
                              void* d_out, int out_size){
  (void)in_sizes; (void)n_in; (void)out_size;
  const float* x         = (const float*)d_in[0];
  const float* conv1_w   = (const float*)d_in[1];
  const float* conv1_b   = (const float*)d_in[2];
  const float* conv2_w   = (const float*)d_in[3];
  const float* conv2_b   = (const float*)d_in[4];
  const float* ln_f_g    = (const float*)d_in[5];
  const float* ln_f_b    = (const float*)d_in[6];
  const float* trend_w   = (const float*)d_in[7];
  const float* trend_b   = (const float*)d_in[8];
  const float* season_w  = (const float*)d_in[9];
  const float* season_b  = (const float*)d_in[10];
  const float* attn_in_w = (const float*)d_in[11];
  const float* attn_in_b = (const float*)d_in[12];
  const float* attn_out_w= (const float*)d_in[13];
  const float* attn_out_b= (const float*)d_in[14];
  const float* ln1_g     = (const float*)d_in[15];
  const float* ln1_b     = (const float*)d_in[16];
  const float* ff1_w     = (const float*)d_in[17];
  const float* ff1_b     = (const float*)d_in[18];
  const float* ff2_w     = (const float*)d_in[19];
  const float* ff2_b     = (const float*)d_in[20];
  const float* ln2_g     = (const float*)d_in[21];
  const float* ln2_b     = (const float*)d_in[22];
  const float* fc_w      = (const float*)d_in[23];
  const float* fc_b      = (const float*)d_in[24];

  // Features: conv1 -> im2col, conv2 GEMM (+relu), LN_f
  conv1_kernel<<<32, 256>>>(x, conv1_w, conv1_b);
  gemm_k<64,64,0><<<dim3(4,10,1), 256>>>(0, 768, 768, conv2_w, nullptr, 768,
                                         conv2_b, nullptr, -1, 5, 256, 0, 1);
  ln_kernel<<<640, 256>>>(5, -1, ln_f_g, ln_f_b, 1);

  // h = hf + (hf@trend^T + tb) + sin(hf@season^T + sb)
  gemm_k<32,64,1><<<dim3(4,20,1), 128>>>(1, 256, 256, trend_w, season_w, 256,
                                         trend_b, season_b, 1, 2, 256, 0, 2);

  for (int i = 0; i < 4; i++){
    // QKV projection
    gemm_k<64,64,0><<<dim3(12,10,1), 256>>>(2, 256, 256,
        attn_in_w + i*768*256, nullptr, 256,
        attn_in_b + i*768, nullptr, -1, 3, 768, 0, 0);
    // block attention
    attn_kernel<<<32, 256>>>();
    // output projection + bias + residual
    gemm_k<32,64,0><<<dim3(4,20,1), 128>>>(6, 256, 256,
        attn_out_w + i*256*256, nullptr, 256,
        attn_out_b + i*256, nullptr, 2, 5, 256, 0, 3);
    ln_kernel<<<640, 256>>>(5, -1, ln1_g + i*256, ln1_b + i*256, 2);
    // FF1 (relu)
    gemm_k<64,64,0><<<dim3(16,10,1), 256>>>(2, 256, 256,
        ff1_w + i*1024*256, nullptr, 256,
        ff1_b + i*1024, nullptr, -1, 4, 1024, 0, 1);
    // FF2 split-K=4 -> partials
    gemm_k<64,64,0><<<dim3(4,10,4), 256>>>(4, 1024, 256,
        ff2_w + i*256*1024, nullptr, 1024,
        nullptr, nullptr, -1, 7, 256, NTOK*256, 4);
    // sum partials + bias + residual + LN
    ln_ff2_kernel<<<640, 256>>>(ff2_b + i*256, ln2_g + i*256, ln2_b + i*256);
  }

  final_kernel<<<1, 512>>>(fc_w, fc_b, (float*)d_out);
}

// round 3
// speedup vs baseline: 1.2141x; 1.2141x over previous
#include <cuda_runtime.h>
#include <math.h>

// ---------------------------------------------------------------------------
// AdvancedAutoInformer — reduced-domain implementation, v2.
// Only token t=3999 matters; attention is block-local (BLOCK=20) => compute
// tokens [3980,4000) from x[3978..3999]. B=32, S=20, D=256, H=8, F=1024, L=4.
// v2: all GEMMs re-gridded for occupancy (>=300 CTAs via BM=32/BN=64 tiles +
// split-K), with every split-K reduction fused into the following
// elementwise/LN/attention kernel.
// ---------------------------------------------------------------------------

#define BATCH 32
#define SEQ   20
#define NTOK  (BATCH*SEQ)     // 640
#define N1    (NTOK*256)      // 163840

// Scratch (static device arrays; no runtime allocation).
__device__ __align__(16) float g_c1col[NTOK*768];     // im2col of conv1 output
__device__ __align__(16) float g_hf  [N1];
__device__ __align__(16) float g_h   [N1];
__device__ __align__(16) float g_qkvp[2*NTOK*768];    // qkv split-K partials
__device__ __align__(16) float g_hid [NTOK*1024];
__device__ __align__(16) float g_att [N1];
__device__ __align__(16) float g_part[8*N1];          // generic split-K partials

__device__ __forceinline__ float* resolve(int s){
  switch(s){
    case 0: return g_c1col;
    case 1: return g_hf;
    case 2: return g_h;
    case 3: return g_qkvp;
    case 4: return g_hid;
    case 5: return g_att;
    case 6: return g_part;
  }
  return nullptr;
}

// ---------------------------------------------------------------------------
// conv1 (C=16 -> D=256, k=3, SAME) + relu, scattered into im2col layout:
// g_c1col[(b*20+i)*768 + d*3 + k] = c1[b, 3979+i+k, d]
// ---------------------------------------------------------------------------
__global__ void conv1_kernel(const float* __restrict__ x,
                             const float* __restrict__ w,
                             const float* __restrict__ bias){
  __shared__ float xs[23*16];          // t = 3978..3999, row 22 = zero pad
  int b = blockIdx.x, tid = threadIdx.x;
  for (int idx = tid; idx < 23*16; idx += 256){
    int j = idx >> 4, c = idx & 15;
    int t = 3978 + j;
    xs[idx] = (t < 4000) ? x[(b*4000 + t)*16 + c] : 0.f;
  }
  __syncthreads();
  int d = tid;
  float wr[48];
  #pragma unroll
  for (int q = 0; q < 48; q++) wr[q] = w[d*48 + q];
  float bb = bias[d];
  // p indexes c1 at global t = 3979+p; p=21 is zero pad (t=4000).
  for (int p = 0; p < 22; p++){
    float val = 0.f;
    if (p < 21){
      float acc = bb;
      #pragma unroll
      for (int k = 0; k < 3; k++)
        #pragma unroll
        for (int c = 0; c < 16; c++)
          acc += wr[c*3 + k] * xs[(p + k)*16 + c];
      val = fmaxf(acc, 0.f);
    }
    #pragma unroll
    for (int k = 0; k < 3; k++){
      int i = p - k;
      if (i >= 0 && i < 20)
        g_c1col[(b*20 + i)*768 + d*3 + k] = val;
    }
  }
}

// ---------------------------------------------------------------------------
// Tiled GEMM: C[m][n] = sum_k A[m][k0+k] * W[n][k0+k]  (NT layout)
// blockIdx.z: split-K chunk (k0 = z*klen, C += z*czstride).
// modes: 0 = +bias   1 = relu(+bias)   4 = raw partial (DUAL: also acc2)
// ---------------------------------------------------------------------------
template<int BM, int BN, int DUAL>
__global__ void gemm_k(int a_sel, int lda, int klen,
                       const float* __restrict__ W,
                       const float* __restrict__ W2, int ldw,
                       const float* __restrict__ b1,
                       int c_sel, int N, int czstride, int c2_off, int mode)
{
  constexpr int NT = (BM/4)*(BN/4);
  constexpr int LA = BM + 4, LB = BN + 4;
  __shared__ float As[16*LA];
  __shared__ float Ws[16*LB];
  __shared__ float Ws2[DUAL ? 16*LB : 4];

  const float* A = resolve(a_sel);
  float* C = resolve(c_sel) + blockIdx.z * czstride;
  int tid = threadIdx.x;
  int tx = tid % (BN/4), ty = tid / (BN/4);
  int m0 = blockIdx.y * BM, n0 = blockIdx.x * BN;
  int k0 = blockIdx.z * klen;

  float acc[16];
  float acc2[DUAL ? 16 : 1];
  #pragma unroll
  for (int q = 0; q < 16; q++) acc[q] = 0.f;
  if (DUAL){
    #pragma unroll
    for (int q = 0; q < (DUAL ? 16 : 1); q++) acc2[q] = 0.f;
  }

  for (int kt = 0; kt < klen; kt += 16){
    for (int idx = tid; idx < BM*4; idx += NT){
      int r = idx >> 2, c4 = idx & 3;
      const float4 v = *(const float4*)&A[(m0 + r)*lda + k0 + kt + c4*4];
      As[(c4*4+0)*LA + r] = v.x;
      As[(c4*4+1)*LA + r] = v.y;
      As[(c4*4+2)*LA + r] = v.z;
      As[(c4*4+3)*LA + r] = v.w;
    }
    for (int idx = tid; idx < BN*4; idx += NT){
      int r = idx >> 2, c4 = idx & 3;
      const float4 v = *(const float4*)&W[(n0 + r)*ldw + k0 + kt + c4*4];
      Ws[(c4*4+0)*LB + r] = v.x;
      Ws[(c4*4+1)*LB + r] = v.y;
      Ws[(c4*4+2)*LB + r] = v.z;
      Ws[(c4*4+3)*LB + r] = v.w;
      if (DUAL){
        const float4 u = *(const float4*)&W2[(n0 + r)*ldw + k0 + kt + c4*4];
        Ws2[(c4*4+0)*LB + r] = u.x;
        Ws2[(c4*4+1)*LB + r] = u.y;
        Ws2[(c4*4+2)*LB + r] = u.z;
        Ws2[(c4*4+3)*LB + r] = u.w;
      }
    }
    __syncthreads();
    #pragma unroll
    for (int k = 0; k < 16; k++){
      float4 a = *(const float4*)&As[k*LA + ty*4];
      float4 w = *(const float4*)&Ws[k*LB + tx*4];
      acc[ 0] += a.x*w.x; acc[ 1] += a.x*w.y; acc[ 2] += a.x*w.z; acc[ 3] += a.x*w.w;
      acc[ 4] += a.y*w.x; acc[ 5] += a.y*w.y; acc[ 6] += a.y*w.z; acc[ 7] += a.y*w.w;
      acc[ 8] += a.z*w.x; acc[ 9] += a.z*w.y; acc[10] += a.z*w.z; acc[11] += a.z*w.w;
      acc[12] += a.w*w.x; acc[13] += a.w*w.y; acc[14] += a.w*w.z; acc[15] += a.w*w.w;
      if (DUAL){
        float4 u = *(const float4*)&Ws2[k*LB + tx*4];
        acc2[ 0] += a.x*u.x; acc2[ 1] += a.x*u.y; acc2[ 2] += a.x*u.z; acc2[ 3] += a.x*u.w;
        acc2[ 4] += a.y*u.x; acc2[ 5] += a.y*u.y; acc2[ 6] += a.y*u.z; acc2[ 7] += a.y*u.w;
        acc2[ 8] += a.z*u.x; acc2[ 9] += a.z*u.y; acc2[10] += a.z*u.z; acc2[11] += a.z*u.w;
        acc2[12] += a.w*u.x; acc2[13] += a.w*u.y; acc2[14] += a.w*u.z; acc2[15] += a.w*u.w;
      }
    }
    __syncthreads();
  }

  #pragma unroll
  for (int r = 0; r < 4; r++){
    int m = m0 + ty*4 + r;
    #pragma unroll
    for (int c = 0; c < 4; c++){
      int n = n0 + tx*4 + c;
      float v = acc[r*4 + c];
      if (mode == 0)      v += b1[n];
      else if (mode == 1) v = fmaxf(v + b1[n], 0.f);
      C[m*N + n] = v;
      if (DUAL && mode == 4) C[c2_off + m*N + n] = acc2[DUAL ? (r*4+c) : 0];
    }
  }
}

// ---------------------------------------------------------------------------
// Block-sum helper (256 threads = one token row).
// ---------------------------------------------------------------------------
__device__ __forceinline__ float block_sum256(float v, float* sh){
  #pragma unroll
  for (int o = 16; o > 0; o >>= 1) v += __shfl_xor_sync(0xffffffffu, v, o);
  if ((threadIdx.x & 31) == 0) sh[threadIdx.x >> 5] = v;
  __syncthreads();
  if (threadIdx.x == 0){
    float s = 0.f;
    #pragma unroll
    for (int w = 0; w < 8; w++) s += sh[w];
    sh[0] = s;
  }
  __syncthreads();
  float r = sh[0];
  __syncthreads();
  return r;
}

__device__ __forceinline__ float ln_finish(float v, float* sh,
                                           const float* g, const float* bta){
  int d = threadIdx.x;
  float mean = block_sum256(v, sh) * (1.f/256.f);
  float c = v - mean;
  float var = block_sum256(c*c, sh) * (1.f/256.f);
  return c * rsqrtf(var + 1e-5f) * g[d] + bta[d];
}

// conv2 split-K reduce + bias + relu + LN_f -> g_hf
__global__ void lnf_kernel(const float* __restrict__ bias,
                           const float* __restrict__ g,
                           const float* __restrict__ bta){
  __shared__ float sh[8];
  int m = blockIdx.x, d = threadIdx.x;
  int idx = m*256 + d;
  float v = g_part[idx] + g_part[N1+idx] + g_part[2*N1+idx] + g_part[3*N1+idx]
          + bias[d];
  v = fmaxf(v, 0.f);
  g_hf[idx] = ln_finish(v, sh, g, bta);
}

// dual split-K reduce: h = hf + (trend+tb) + sin(season+sb)
__global__ void hcomb_kernel(const float* __restrict__ tb,
                             const float* __restrict__ sb){
  int m = blockIdx.x, d = threadIdx.x;
  int idx = m*256 + d;
  float t = g_part[idx] + g_part[N1+idx] + g_part[2*N1+idx] + g_part[3*N1+idx]
          + tb[d];
  float s = g_part[4*N1+idx] + g_part[5*N1+idx] + g_part[6*N1+idx]
          + g_part[7*N1+idx] + sb[d];
  g_h[idx] = g_hf[idx] + t + sinf(s);
}

// residual + 4-way split-K reduce + bias + LN -> g_h (used for ln1 and ln2)
__global__ void ln_res4_kernel(const float* __restrict__ bias,
                               const float* __restrict__ g,
                               const float* __restrict__ bta){
  __shared__ float sh[8];
  int m = blockIdx.x, d = threadIdx.x;
  int idx = m*256 + d;
  float v = g_h[idx] + bias[d]
          + g_part[idx] + g_part[N1+idx] + g_part[2*N1+idx] + g_part[3*N1+idx];
  g_h[idx] = ln_finish(v, sh, g, bta);
}

// ---------------------------------------------------------------------------
// Attention: one warp per (batch, head). Fuses the QKV split-K(2) reduce +
// bias. Reads g_qkvp, writes g_att.
// ---------------------------------------------------------------------------
__global__ void attn_kernel(const float* __restrict__ bias){
  __shared__ float sk[20*32], sv[20*32];
  int bh = blockIdx.x;
  int b = bh >> 3, h = bh & 7;
  int lane = threadIdx.x;
  const float* P0 = g_qkvp;
  const float* P1 = g_qkvp + NTOK*768;
  int base = b*20*768 + h*32;
  for (int idx = lane; idx < 640; idx += 32){
    int j = idx >> 5, t = idx & 31;
    int o = base + j*768 + t;
    sk[idx] = P0[o+256] + P1[o+256] + bias[256 + h*32 + t];
    sv[idx] = P0[o+512] + P1[o+512] + bias[512 + h*32 + t];
  }
  __syncwarp();
  if (lane < 20){
    int i = lane;
    float qr[32];
    int qo = base + i*768;
    #pragma unroll
    for (int t = 0; t < 32; t++)
      qr[t] = P0[qo+t] + P1[qo+t] + bias[h*32 + t];
    float sc[20];
    float mx = -1e30f;
    for (int j = 0; j < 20; j++){
      float d = 0.f;
      #pragma unroll
      for (int t = 0; t < 32; t++) d += qr[t]*sk[j*32 + t];
      d *= 0.17677669529663687f;   // 1/sqrt(32)
      sc[j] = d;
      mx = fmaxf(mx, d);
    }
    float s = 0.f;
    for (int j = 0; j < 20; j++){ sc[j] = expf(sc[j] - mx); s += sc[j]; }
    float inv = 1.f / s;
    float* op = g_att + (b*20 + i)*256 + h*32;
    for (int t = 0; t < 32; t++){
      float o = 0.f;
      for (int j = 0; j < 20; j++) o += sc[j]*sv[j*32 + t];
      op[t] = o * inv;
    }
  }
}

// ---------------------------------------------------------------------------
// Final projection: out[b] = h[b, last] @ fc_w^T + fc_b.
// ---------------------------------------------------------------------------
__global__ void final_kernel(const float* __restrict__ fw,
                             const float* __restrict__ fb,
                             float* __restrict__ out){
  int tid = threadIdx.x;
  int b = tid >> 4, c = tid & 15;
  const float* hr = g_h + (b*20 + 19)*256;
  const float* wr = fw + c*256;
  float acc = fb[c];
  for (int d = 0; d < 256; d++) acc += hr[d]*wr[d];
  out[tid] = acc;
}

// ---------------------------------------------------------------------------
extern "C" void kernel_launch(void* const* d_in, const int* in_sizes, int n_in,
                              void* d_out, int out_size){
  (void)in_sizes; (void)n_in; (void)out_size;
  const float* x         = (const float*)d_in[0];
  const float* conv1_w   = (const float*)d_in[1];
  const float* conv1_b   = (const float*)d_in[2];
  const float* conv2_w   = (const float*)d_in[3];
  const float* conv2_b   = (const float*)d_in[4];
  const float* ln_f_g    = (const float*)d_in[5];
  const float* ln_f_b    = (const float*)d_in[6];
  const float* trend_w   = (const float*)d_in[7];
  const float* trend_b   = (const float*)d_in[8];
  const float* season_w  = (const float*)d_in[9];
  const float* season_b  = (const float*)d_in[10];
  const float* attn_in_w = (const float*)d_in[11];
  const float* attn_in_b = (const float*)d_in[12];
  const float* attn_out_w= (const float*)d_in[13];
  const float* attn_out_b= (const float*)d_in[14];
  const float* ln1_g     = (const float*)d_in[15];
  const float* ln1_b     = (const float*)d_in[16];
  const float* ff1_w     = (const float*)d_in[17];
  const float* ff1_b     = (const float*)d_in[18];
  const float* ff2_w     = (const float*)d_in[19];
  const float* ff2_b     = (const float*)d_in[20];
  const float* ln2_g     = (const float*)d_in[21];
  const float* ln2_b     = (const float*)d_in[22];
  const float* fc_w      = (const float*)d_in[23];
  const float* fc_b      = (const float*)d_in[24];

  // conv1 -> im2col
  conv1_kernel<<<32, 256>>>(x, conv1_w, conv1_b);
  // conv2 GEMM: 640x256, K=768, split-K 4 -> partials
  gemm_k<32,64,0><<<dim3(4,20,4), 128>>>(0, 768, 192, conv2_w, nullptr, 768,
                                         nullptr, 6, 256, N1, 0, 4);
  // reduce + bias + relu + LN_f
  lnf_kernel<<<640, 256>>>(conv2_b, ln_f_g, ln_f_b);
  // trend+season dual GEMM: 640x256, K=256, split-K 4 -> dual partials
  gemm_k<32,64,1><<<dim3(4,20,4), 128>>>(1, 256, 64, trend_w, season_w, 256,
                                         nullptr, 6, 256, N1, 4*N1, 4);
  // h = hf + (trend+tb) + sin(season+sb)
  hcomb_kernel<<<640, 256>>>(trend_b, season_b);

  for (int i = 0; i < 4; i++){
    // QKV GEMM: 640x768, K=256, split-K 2 -> partials (bias fused into attn)
    gemm_k<32,64,0><<<dim3(12,20,2), 128>>>(2, 256, 128,
        attn_in_w + i*768*256, nullptr, 256,
        nullptr, 3, 768, NTOK*768, 0, 4);
    // block attention (one warp per batch-head), fuses qkv reduce + bias
    attn_kernel<<<256, 32>>>(attn_in_b + i*768);
    // output projection: 640x256, K=256, split-K 4 -> partials
    gemm_k<32,64,0><<<dim3(4,20,4), 128>>>(5, 256, 64,
        attn_out_w + i*256*256, nullptr, 256,
        nullptr, 6, 256, N1, 0, 4);
    // residual + reduce + bias + LN1
    ln_res4_kernel<<<640, 256>>>(attn_out_b + i*256, ln1_g + i*256, ln1_b + i*256);
    // FF1: 640x1024, K=256, relu(+bias)
    gemm_k<32,64,0><<<dim3(16,20,1), 128>>>(2, 256, 256,
        ff1_w + i*1024*256, nullptr, 256,
        ff1_b + i*1024, 4, 1024, 0, 0, 1);
    // FF2: 640x256, K=1024, split-K 4 -> partials
    gemm_k<32,64,0><<<dim3(4,20,4), 128>>>(4, 1024, 256,
        ff2_w + i*256*1024, nullptr, 1024,
        nullptr, 6, 256, N1, 0, 4);
    // residual + reduce + bias + LN2
    ln_res4_kernel<<<640, 256>>>(ff2_b + i*256, ln2_g + i*256, ln2_b + i*256);
  }

  final_kernel<<<1, 512>>>(fc_w, fc_b, (float*)d_out);
}

// round 6
// speedup vs baseline: 1.5147x; 1.2476x over previous
#include <cuda_runtime.h>
#include <math.h>

// ---------------------------------------------------------------------------
// AdvancedAutoInformer — persistent megakernel (v5).
// Domain reduction: only token 3999 matters; block-local attention (BLOCK=20)
// => tokens [3980,4000) from x[3978..3999]. B=32, S=20, D=256, H=8, F=1024.
// One kernel, 148 CTAs x 512 threads (1 CTA/SM), phases separated by a
// device-wide counter barrier. GEMM uses packed fma.rn.f32x2 with
// double-buffered smem. v5 fix: FF2 split-K partials go to g_qkvp (12*N1,
// dead at that point) — v4 wrote them past the end of g_part (OOB crash).
// ---------------------------------------------------------------------------

#define NCTA  148
#define NTHR  512
#define NTOK  640
#define N1    (NTOK*256)
#define LA    68
#define LW    260
#define POOLF 10496    // floats: 2*16*LA + 2*16*LW = 2176 + 8320

// Scratch (static device arrays; zero runtime allocation).
__device__ __align__(16) float g_c1col[NTOK*768];
__device__ __align__(16) float g_hf  [N1];
__device__ __align__(16) float g_h   [N1];
__device__ __align__(16) float g_qkvp[4*NTOK*768];   // 12*N1: QKV partials / FF2 partials
__device__ __align__(16) float g_att [N1];
__device__ __align__(16) float g_part[12*N1];        // split-K partial chunks
__device__ unsigned g_bars[64];
__device__ unsigned g_done;

// ---------------- device-wide barrier (148 co-resident CTAs) ----------------
__device__ __forceinline__ void gsync(int id){
  __syncthreads();
  if (threadIdx.x == 0){
    __threadfence();                       // cumulative release
    atomicAdd(&g_bars[id], 1u);
    volatile unsigned* p = &g_bars[id];
    while (*p < NCTA) { }
    __threadfence();                       // acquire
  }
  __syncthreads();
}

// ---------------- f32x2 helpers ----------------
__device__ __forceinline__ unsigned long long pk2f(float x){
  unsigned long long r;
  asm("mov.b64 %0, {%1, %1};" : "=l"(r) : "f"(x));
  return r;
}
__device__ __forceinline__ void fma2(unsigned long long &d,
                                     unsigned long long a, unsigned long long b){
  asm("fma.rn.f32x2 %0, %1, %2, %0;" : "+l"(d) : "l"(a), "l"(b));
}
__device__ __forceinline__ void unpk(unsigned long long v, float& lo, float& hi){
  asm("mov.b64 {%0, %1}, %2;" : "=f"(lo), "=f"(hi) : "l"(v));
}

// ---------------------------------------------------------------------------
// GEMM phase: C[m][n] = sum_k Aeff[m][k0+k] * Wrow(n)[k0+k]   (NT layout)
// Aeff = A  (A2==nullptr)  or  relu(A + A2 + abias[k])  (FF1->FF2 fusion).
// Tile 64x256 per job, 512 threads, per-thread 4 rows x 8 cols (cols split
// {tx*4, 128+tx*4} for conflict-free LDS.128). Double-buffered smem.
// Wrow(n) = W0 + n*ldw for n<wsplit else W1 + (n-wsplit)*ldw.
// mode: 0 = raw partial store, 1 = relu(acc + bias).
// ---------------------------------------------------------------------------
__device__ void gemm_dev(float* pool,
    const float* __restrict__ A, const float* __restrict__ A2,
    const float* __restrict__ abias, int lda,
    const float* __restrict__ W0, const float* __restrict__ W1,
    int wsplit, int ldw,
    const float* __restrict__ bias, int mode,
    float* C, int N, int splitk, int klen)
{
  const int tiles_n = N >> 8;
  const int njobs = 10 * tiles_n * splitk;
  float* As = pool;                 // [2][16][LA]
  float* Ws = pool + 2*16*LA;       // [2][16][LW]
  const int tid = threadIdx.x;
  const int tx = tid & 31, ty = tid >> 5;
  const int lr = tid >> 2, lc = (tid & 3) * 4;

  for (int job = blockIdx.x; job < njobs; job += NCTA){
    int z    = job / (10*tiles_n);
    int rest = job - z*(10*tiles_n);
    int tm   = rest / tiles_n;
    int tn   = rest - tm*tiles_n;
    int m0 = tm*64, n0 = tn*256, k0 = z*klen;

    int nA = n0 + lr, nB = n0 + 128 + lr;
    const float* WrA = (nA < wsplit) ? W0 + nA*ldw : W1 + (nA - wsplit)*ldw;
    const float* WrB = (nB < wsplit) ? W0 + nB*ldw : W1 + (nB - wsplit)*ldw;
    const float* Ar  = A + (m0 + lr)*lda;           // deref only if tid<256
    const float* Ar2 = A2 ? A2 + (m0 + lr)*lda : nullptr;

    unsigned long long acc[16];
    #pragma unroll
    for (int q = 0; q < 16; q++) acc[q] = 0ULL;

    const int nslab = klen >> 4;
    float4 ra, rwa, rwb;
    {
      int kk = k0 + lc;
      if (tid < 256){
        ra = *(const float4*)(Ar + kk);
        if (A2){
          float4 rb = *(const float4*)(Ar2 + kk);
          float4 bb = *(const float4*)(abias + kk);
          ra.x = fmaxf(ra.x + rb.x + bb.x, 0.f);
          ra.y = fmaxf(ra.y + rb.y + bb.y, 0.f);
          ra.z = fmaxf(ra.z + rb.z + bb.z, 0.f);
          ra.w = fmaxf(ra.w + rb.w + bb.w, 0.f);
        }
      }
      rwa = *(const float4*)(WrA + kk);
      rwb = *(const float4*)(WrB + kk);
    }
    // store slab 0 -> buffer 0 (transposed: [k][m] / [k][n])
    {
      if (tid < 256){
        As[(lc+0)*LA + lr] = ra.x; As[(lc+1)*LA + lr] = ra.y;
        As[(lc+2)*LA + lr] = ra.z; As[(lc+3)*LA + lr] = ra.w;
      }
      Ws[(lc+0)*LW + lr] = rwa.x; Ws[(lc+1)*LW + lr] = rwa.y;
      Ws[(lc+2)*LW + lr] = rwa.z; Ws[(lc+3)*LW + lr] = rwa.w;
      Ws[(lc+0)*LW + 128 + lr] = rwb.x; Ws[(lc+1)*LW + 128 + lr] = rwb.y;
      Ws[(lc+2)*LW + 128 + lr] = rwb.z; Ws[(lc+3)*LW + 128 + lr] = rwb.w;
    }
    __syncthreads();

    int p = 0;
    for (int s = 0; s < nslab; s++){
      if (s + 1 < nslab){
        int kk = k0 + (s+1)*16 + lc;
        if (tid < 256){
          ra = *(const float4*)(Ar + kk);
          if (A2){
            float4 rb = *(const float4*)(Ar2 + kk);
            float4 bb = *(const float4*)(abias + kk);
            ra.x = fmaxf(ra.x + rb.x + bb.x, 0.f);
            ra.y = fmaxf(ra.y + rb.y + bb.y, 0.f);
            ra.z = fmaxf(ra.z + rb.z + bb.z, 0.f);
            ra.w = fmaxf(ra.w + rb.w + bb.w, 0.f);
          }
        }
        rwa = *(const float4*)(WrA + kk);
        rwb = *(const float4*)(WrB + kk);
      }
      const float* Ab = As + p*16*LA;
      const float* Wb = Ws + p*16*LW;
      #pragma unroll
      for (int k = 0; k < 16; k++){
        float4 a = *(const float4*)(Ab + k*LA + ty*4);       // broadcast
        ulonglong2 wA = *(const ulonglong2*)(Wb + k*LW + tx*4);
        ulonglong2 wB = *(const ulonglong2*)(Wb + k*LW + 128 + tx*4);
        unsigned long long ax = pk2f(a.x), ay = pk2f(a.y),
                           az = pk2f(a.z), aw = pk2f(a.w);
        fma2(acc[ 0], ax, wA.x); fma2(acc[ 1], ax, wA.y);
        fma2(acc[ 2], ax, wB.x); fma2(acc[ 3], ax, wB.y);
        fma2(acc[ 4], ay, wA.x); fma2(acc[ 5], ay, wA.y);
        fma2(acc[ 6], ay, wB.x); fma2(acc[ 7], ay, wB.y);
        fma2(acc[ 8], az, wA.x); fma2(acc[ 9], az, wA.y);
        fma2(acc[10], az, wB.x); fma2(acc[11], az, wB.y);
        fma2(acc[12], aw, wA.x); fma2(acc[13], aw, wA.y);
        fma2(acc[14], aw, wB.x); fma2(acc[15], aw, wB.y);
      }
      if (s + 1 < nslab){
        float* Ab2 = As + (p^1)*16*LA;
        float* Wb2 = Ws + (p^1)*16*LW;
        if (tid < 256){
          Ab2[(lc+0)*LA + lr] = ra.x; Ab2[(lc+1)*LA + lr] = ra.y;
          Ab2[(lc+2)*LA + lr] = ra.z; Ab2[(lc+3)*LA + lr] = ra.w;
        }
        Wb2[(lc+0)*LW + lr] = rwa.x; Wb2[(lc+1)*LW + lr] = rwa.y;
        Wb2[(lc+2)*LW + lr] = rwa.z; Wb2[(lc+3)*LW + lr] = rwa.w;
        Wb2[(lc+0)*LW + 128 + lr] = rwb.x; Wb2[(lc+1)*LW + 128 + lr] = rwb.y;
        Wb2[(lc+2)*LW + 128 + lr] = rwb.z; Wb2[(lc+3)*LW + 128 + lr] = rwb.w;
      }
      __syncthreads();
      p ^= 1;
    }

    // epilogue
    float* Cz = C + (long)z * 640 * N;
    #pragma unroll
    for (int r = 0; r < 4; r++){
      int m = m0 + ty*4 + r;
      float o0,o1,o2,o3,o4,o5,o6,o7;
      unpk(acc[r*4+0], o0, o1); unpk(acc[r*4+1], o2, o3);
      unpk(acc[r*4+2], o4, o5); unpk(acc[r*4+3], o6, o7);
      int na = n0 + tx*4, nb = n0 + 128 + tx*4;
      if (mode == 1){
        o0 = fmaxf(o0 + bias[na+0], 0.f); o1 = fmaxf(o1 + bias[na+1], 0.f);
        o2 = fmaxf(o2 + bias[na+2], 0.f); o3 = fmaxf(o3 + bias[na+3], 0.f);
        o4 = fmaxf(o4 + bias[nb+0], 0.f); o5 = fmaxf(o5 + bias[nb+1], 0.f);
        o6 = fmaxf(o6 + bias[nb+2], 0.f); o7 = fmaxf(o7 + bias[nb+3], 0.f);
      }
      *(float4*)&Cz[(long)m*N + na] = make_float4(o0,o1,o2,o3);
      *(float4*)&Cz[(long)m*N + nb] = make_float4(o4,o5,o6,o7);
    }
  }
}

// ---------------------------------------------------------------------------
// conv1 (C=16 -> D=256, k=3, SAME) + relu -> im2col layout in g_c1col.
// ---------------------------------------------------------------------------
__device__ void conv1_dev(float* pool, const float* __restrict__ x,
                          const float* __restrict__ w,
                          const float* __restrict__ bias){
  if (blockIdx.x < 32){
    float* xs = pool;                       // 23*16 floats
    int b = blockIdx.x, tid = threadIdx.x;
    for (int idx = tid; idx < 23*16; idx += NTHR){
      int j = idx >> 4, c = idx & 15;
      int t = 3978 + j;
      xs[idx] = (t < 4000) ? x[(b*4000 + t)*16 + c] : 0.f;
    }
    __syncthreads();
    if (tid < 256){
      int d = tid;
      float wr[48];
      #pragma unroll
      for (int q = 0; q < 48; q++) wr[q] = w[d*48 + q];
      float bb = bias[d];
      for (int p = 0; p < 22; p++){
        float val = 0.f;
        if (p < 21){
          float acc = bb;
          #pragma unroll
          for (int k = 0; k < 3; k++)
            #pragma unroll
            for (int c = 0; c < 16; c++)
              acc += wr[c*3 + k] * xs[(p + k)*16 + c];
          val = fmaxf(acc, 0.f);
        }
        #pragma unroll
        for (int k = 0; k < 3; k++){
          int i = p - k;
          if (i >= 0 && i < 20)
            g_c1col[(b*20 + i)*768 + d*3 + k] = val;
        }
      }
    }
    __syncthreads();
  }
}

// ---------------------------------------------------------------------------
// Warp-per-row LayerNorm family (row = 256 floats, 8 per lane, strided).
// ---------------------------------------------------------------------------
__device__ __forceinline__ float wsum(float v){
  #pragma unroll
  for (int o = 16; o > 0; o >>= 1) v += __shfl_xor_sync(0xffffffffu, v, o);
  return v;
}

// out[m] = LN( (res?res[m]:0) + bias + sum_{c<nch} part[c*chs + m*256 + :] )
// with optional relu before LN.
__device__ void ln_rows(const float* __restrict__ res,
                        const float* __restrict__ part, int nch, int chs,
                        const float* __restrict__ bias,
                        const float* __restrict__ g,
                        const float* __restrict__ bta,
                        float* __restrict__ out, int relu){
  int gw = blockIdx.x*16 + (threadIdx.x >> 5);
  if (gw >= NTOK) return;
  int lane = threadIdx.x & 31;
  int base = gw*256;
  float v[8];
  float s = 0.f;
  #pragma unroll
  for (int q = 0; q < 8; q++){
    int d = q*32 + lane;
    float t = bias[d];
    for (int c = 0; c < nch; c++) t += part[c*chs + base + d];
    if (res) t += res[base + d];
    if (relu) t = fmaxf(t, 0.f);
    v[q] = t; s += t;
  }
  float mean = wsum(s) * (1.f/256.f);
  float s2 = 0.f;
  #pragma unroll
  for (int q = 0; q < 8; q++){ float c = v[q]-mean; s2 += c*c; }
  float inv = rsqrtf(wsum(s2) * (1.f/256.f) + 1e-5f);
  #pragma unroll
  for (int q = 0; q < 8; q++){
    int d = q*32 + lane;
    out[base + d] = (v[q]-mean)*inv*g[d] + bta[d];
  }
}

// h = hf + (trend + tb) + sin(season + sb); dual partials: 4 chunks of 640x512.
__device__ void hcomb_dev(const float* __restrict__ tb,
                          const float* __restrict__ sb){
  int gw = blockIdx.x*16 + (threadIdx.x >> 5);
  if (gw >= NTOK) return;
  int lane = threadIdx.x & 31;
  #pragma unroll
  for (int q = 0; q < 8; q++){
    int d = q*32 + lane;
    int o = gw*512 + d;
    float tr = g_part[o] + g_part[2*N1 + o] + g_part[4*N1 + o] + g_part[6*N1 + o] + tb[d];
    float se = g_part[o+256] + g_part[2*N1+o+256] + g_part[4*N1+o+256] + g_part[6*N1+o+256] + sb[d];
    g_h[gw*256 + d] = g_hf[gw*256 + d] + tr + sinf(se);
  }
}

// ---------------------------------------------------------------------------
// Attention: CTA per batch; fuses QKV 4-chunk split-K reduce + bias.
// ---------------------------------------------------------------------------
__device__ void attn_dev(float* pool, const float* __restrict__ bias){
  if (blockIdx.x < 32){
    int b = blockIdx.x, tid = threadIdx.x;
    float* skv = pool;                       // 20*512 floats
    const int CH = NTOK*768;
    for (int idx = tid; idx < 20*512; idx += NTHR){
      int j = idx >> 9, e = idx & 511;
      int o = (b*20 + j)*768 + 256 + e;
      skv[idx] = g_qkvp[o] + g_qkvp[CH+o] + g_qkvp[2*CH+o] + g_qkvp[3*CH+o]
               + bias[256 + e];
    }
    __syncthreads();
    if (tid < 160){
      int h = tid / 20, i = tid % 20;
      float qr[32];
      int qo = (b*20 + i)*768 + h*32;
      #pragma unroll
      for (int t = 0; t < 32; t++)
        qr[t] = g_qkvp[qo+t] + g_qkvp[CH+qo+t] + g_qkvp[2*CH+qo+t]
              + g_qkvp[3*CH+qo+t] + bias[h*32 + t];
      float sc[20];
      float mx = -1e30f;
      for (int j = 0; j < 20; j++){
        const float* kp = &skv[j*512 + h*32];
        float d = 0.f;
        #pragma unroll
        for (int t = 0; t < 32; t++) d += qr[t]*kp[t];
        d *= 0.17677669529663687f;       // 1/sqrt(32)
        sc[j] = d;
        mx = fmaxf(mx, d);
      }
      float s = 0.f;
      for (int j = 0; j < 20; j++){ sc[j] = expf(sc[j] - mx); s += sc[j]; }
      float inv = 1.f / s;
      float* op = g_att + (b*20 + i)*256 + h*32;
      for (int t = 0; t < 32; t++){
        float o = 0.f;
        for (int j = 0; j < 20; j++) o += sc[j]*skv[j*512 + 256 + h*32 + t];
        op[t] = o * inv;
      }
    }
    __syncthreads();
  }
}

// ---------------------------------------------------------------------------
// Final: out[b*16+c] = h[b,last,:] . fc_w[c,:] + fc_b[c]  (warp per output)
// ---------------------------------------------------------------------------
__device__ void final_dev(const float* __restrict__ fw,
                          const float* __restrict__ fb,
                          float* __restrict__ out){
  int gw = blockIdx.x*16 + (threadIdx.x >> 5);
  if (gw >= 512) return;
  int lane = threadIdx.x & 31;
  int b = gw >> 4, c = gw & 15;
  const float* hr = g_h + (b*20 + 19)*256;
  const float* wr = fw + c*256;
  float s = 0.f;
  #pragma unroll
  for (int q = 0; q < 8; q++){
    int d = q*32 + lane;
    s += hr[d]*wr[d];
  }
  s = wsum(s);
  if (lane == 0) out[gw] = s + fb[c];
}

// ---------------------------------------------------------------------------
__global__ void __launch_bounds__(NTHR, 1)
mega_kernel(const float* x,
            const float* c1w, const float* c1b,
            const float* c2w, const float* c2b,
            const float* lnfg, const float* lnfb,
            const float* tw, const float* tb,
            const float* sw, const float* sb,
            const float* aiw, const float* aib,
            const float* aow, const float* aob,
            const float* l1g, const float* l1b,
            const float* f1w, const float* f1b,
            const float* f2w, const float* f2b,
            const float* l2g, const float* l2b,
            const float* fcw, const float* fcb,
            float* out)
{
  __shared__ __align__(16) float pool[POOLF];
  int bar = 0;

  conv1_dev(pool, x, c1w, c1b);
  gsync(bar++);
  // conv2: 640x256, K=768, splitK 12 (klen 64) -> 12 chunks = exactly g_part
  gemm_dev(pool, g_c1col, nullptr, nullptr, 768, c2w, nullptr, 1<<30, 768,
           nullptr, 0, g_part, 256, 12, 64);
  gsync(bar++);
  ln_rows(nullptr, g_part, 12, N1, c2b, lnfg, lnfb, g_hf, 1);
  gsync(bar++);
  // trend|season concat: N=512, K=256, splitK 4 -> 4 chunks of 640x512 (8*N1)
  gemm_dev(pool, g_hf, nullptr, nullptr, 256, tw, sw, 256, 256,
           nullptr, 0, g_part, 512, 4, 64);
  gsync(bar++);
  hcomb_dev(tb, sb);
  gsync(bar++);

  for (int i = 0; i < 4; i++){
    // QKV: N=768, K=256, splitK 4 -> 4 chunks of 3*N1 = exactly g_qkvp
    gemm_dev(pool, g_h, nullptr, nullptr, 256, aiw + i*768*256, nullptr,
             1<<30, 256, nullptr, 0, g_qkvp, 768, 4, 64);
    gsync(bar++);
    attn_dev(pool, aib + i*768);
    gsync(bar++);
    // out-proj: N=256, K=256, splitK 8 (klen 32) -> 8 chunks (8*N1 <= g_part)
    gemm_dev(pool, g_att, nullptr, nullptr, 256, aow + i*256*256, nullptr,
             1<<30, 256, nullptr, 0, g_part, 256, 8, 32);
    gsync(bar++);
    ln_rows(g_h, g_part, 8, N1, aob + i*256, l1g + i*256, l1b + i*256, g_h, 0);
    gsync(bar++);
    // FF1: N=1024, K=256, splitK 2 (klen 128) -> RAW partials, 2 chunks of
    // 640x1024 (4*N1 each) at g_part[0..8*N1)
    gemm_dev(pool, g_h, nullptr, nullptr, 256, f1w + i*1024*256, nullptr,
             1<<30, 256, nullptr, 0, g_part, 1024, 2, 128);
    gsync(bar++);
    // FF2: N=256, K=1024, splitK 8 (klen 128) -> 8 chunks of N1 into g_qkvp
    // (12*N1 buffer, dead here). A = relu(p0 + p1 + ff1_bias) fused in load.
    gemm_dev(pool, g_part, g_part + 640*1024, f1b + i*1024, 1024,
             f2w + i*256*1024, nullptr, 1<<30, 1024,
             nullptr, 0, g_qkvp, 256, 8, 128);
    gsync(bar++);
    ln_rows(g_h, g_qkvp, 8, N1, f2b + i*256, l2g + i*256, l2b + i*256,
            g_h, 0);
    gsync(bar++);
  }

  final_dev(fcw, fcb, out);

  // termination + reset for next graph replay
  __syncthreads();
  if (threadIdx.x == 0){
    __threadfence();
    unsigned old = atomicAdd(&g_done, 1u);
    if (old == NCTA - 1){
      #pragma unroll
      for (int i = 0; i < 64; i++) g_bars[i] = 0;
      g_done = 0;
      __threadfence();
    }
  }
}

// ---------------------------------------------------------------------------
extern "C" void kernel_launch(void* const* d_in, const int* in_sizes, int n_in,
                              void* d_out, int out_size){
  (void)in_sizes; (void)n_in; (void)out_size;
  mega_kernel<<<NCTA, NTHR>>>(
      (const float*)d_in[0],  (const float*)d_in[1],  (const float*)d_in[2],
      (const float*)d_in[3],  (const float*)d_in[4],  (const float*)d_in[5],
      (const float*)d_in[6],  (const float*)d_in[7],  (const float*)d_in[8],
      (const float*)d_in[9],  (const float*)d_in[10], (const float*)d_in[11],
      (const float*)d_in[12], (const float*)d_in[13], (const float*)d_in[14],
      (const float*)d_in[15], (const float*)d_in[16], (const float*)d_in[17],
      (const float*)d_in[18], (const float*)d_in[19], (const float*)d_in[20],
      (const float*)d_in[21], (const float*)d_in[22], (const float*)d_in[23],
      (const float*)d_in[24], (float*)d_out);
}